// round 12
// baseline (speedup 1.0000x reference)
#include <cuda_runtime.h>
#include <cuda_fp8.h>
#include <cstdint>
#include <cstddef>

#define DI __device__ __forceinline__

// ---------------- problem constants ----------------
static constexpr int MT = 8192;   // tokens
static constexpr int NT = 4096;   // out features
static constexpr int KT = 4096;   // in features
static constexpr float FP8MAX = 448.0f;
static constexpr float AMAX_EPS = 1e-8f;
static constexpr float MOMENTUM = 0.95f;

// ---------------- GEMM tiling ----------------
static constexpr int BM = 128;
static constexpr int BN = 128;
static constexpr int BK = 128;                 // e4m3 bytes along K per stage
static constexpr int NSTAGES = 4;
static constexpr int K_ITERS = KT / BK;        // 32
static constexpr int A_BYTES = BM * BK;        // 16384
static constexpr int B_BYTES = BN * BK;        // 16384
static constexpr int STAGE_BYTES = A_BYTES + B_BYTES;   // 32768
static constexpr int DYN_SMEM = NSTAGES * STAGE_BYTES;  // 131072 -> 1 CTA/SM
static constexpr int THREADS = 256;            // 8 warps: 2(m) x 4(n), warp 64x32

// quant grid split
static constexpr int QX_BLOCKS = 1024;
static constexpr int QW_BLOCKS = 512;
static constexpr int Q_BLOCKS  = QX_BLOCKS + QW_BLOCKS;   // 1536

// ---------------- scratch ----------------
__device__ __align__(128) uint8_t g_Xq[(size_t)MT * KT];
__device__ __align__(128) uint8_t g_Wq[(size_t)NT * KT];
__device__ float g_partX[QX_BLOCKS];
__device__ float g_partW[QW_BLOCKS];

// ---------------- PTX helpers (base sm_103 target ONLY) ----------------
DI uint32_t smem_u32(const void* p) {
    uint32_t a;
    asm("{ .reg .u64 t; cvta.to.shared.u64 t, %1; cvt.u32.u64 %0, t; }" : "=r"(a) : "l"(p));
    return a;
}
DI void cp_async16(uint32_t s, const void* g) {
    asm volatile("cp.async.cg.shared.global [%0], [%1], 16;" :: "r"(s), "l"(g) : "memory");
}
DI void cp_commit() { asm volatile("cp.async.commit_group;" ::: "memory"); }
template <int N> DI void cp_wait() {
    asm volatile("cp.async.wait_group %0;" :: "n"(N) : "memory");
}
DI void ldsm_x4(uint32_t& r0, uint32_t& r1, uint32_t& r2, uint32_t& r3, uint32_t addr) {
    asm volatile("ldmatrix.sync.aligned.m8n8.x4.shared.b16 {%0,%1,%2,%3}, [%4];"
                 : "=r"(r0), "=r"(r1), "=r"(r2), "=r"(r3) : "r"(addr));
}
DI void mma_e4m3(float& c0, float& c1, float& c2, float& c3,
                 uint32_t a0, uint32_t a1, uint32_t a2, uint32_t a3,
                 uint32_t b0, uint32_t b1) {
    asm volatile(
        "mma.sync.aligned.m16n8k32.row.col.f32.e4m3.e4m3.f32 "
        "{%0,%1,%2,%3}, {%4,%5,%6,%7}, {%8,%9}, {%0,%1,%2,%3};"
        : "+f"(c0), "+f"(c1), "+f"(c2), "+f"(c3)
        : "r"(a0), "r"(a1), "r"(a2), "r"(a3), "r"(b0), "r"(b1));
}
// pack two scaled floats into e4m3x2 (lo = first arg)
DI uint32_t cvt_e4m3x2(float lo, float hi) {
    uint16_t r;
    asm("cvt.rn.satfinite.e4m3x2.f32 %0, %1, %2;" : "=h"(r) : "f"(hi), "f"(lo));
    return (uint32_t)r;
}

// ---------------- kernel 1: combined quantize X + W, per-block absmax ----------------
__global__ void quant_amax_kernel(const float* __restrict__ x,
                                  const float* __restrict__ w,
                                  const float* __restrict__ in_amax,
                                  const float* __restrict__ w_amax) {
    __shared__ float smax[8];
    const bool isX = (blockIdx.x < QX_BLOCKS);
    const int bid  = isX ? (int)blockIdx.x : (int)blockIdx.x - QX_BLOCKS;
    const int nblk = isX ? QX_BLOCKS : QW_BLOCKS;
    const int n4   = isX ? MT * KT / 4 : NT * KT / 4;
    const float4* src4 = (const float4*)(isX ? x : w);
    uint32_t* dst4 = (uint32_t*)(isX ? g_Xq : g_Wq);
    const float s = FP8MAX / fmaxf((isX ? in_amax : w_amax)[0], AMAX_EPS);

    float lmax = 0.0f;
    for (int i = bid * blockDim.x + threadIdx.x; i < n4; i += nblk * blockDim.x) {
        float4 v = src4[i];
        lmax = fmaxf(lmax, fmaxf(fmaxf(fabsf(v.x), fabsf(v.y)), fmaxf(fabsf(v.z), fabsf(v.w))));
        const uint32_t lo = cvt_e4m3x2(v.x * s, v.y * s);
        const uint32_t hi = cvt_e4m3x2(v.z * s, v.w * s);
        dst4[i] = lo | (hi << 16);
    }
    #pragma unroll
    for (int o = 16; o > 0; o >>= 1) lmax = fmaxf(lmax, __shfl_xor_sync(0xffffffffu, lmax, o));
    if ((threadIdx.x & 31) == 0) smax[threadIdx.x >> 5] = lmax;
    __syncthreads();
    if (threadIdx.x == 0) {
        float b = smax[0];
        #pragma unroll
        for (int ww = 1; ww < 8; ++ww) b = fmaxf(b, smax[ww]);
        (isX ? g_partX : g_partW)[bid] = b;
    }
}

// ---------------- kernel 2: fp8 GEMM with ka-level fragment double-buffering ----------------
__global__ void __launch_bounds__(THREADS, 1) fp8_gemm_kernel(
    const float* __restrict__ bias,
    const float* __restrict__ in_amax,
    const float* __restrict__ w_amax,
    float* __restrict__ out, int out_size)
{
    extern __shared__ uint8_t dynsmem[];
    __shared__ float bias_s[BN];

    const int tid  = threadIdx.x;
    const int wid  = tid >> 5;
    const int lane = tid & 31;
    const int wm   = wid >> 2;        // 0..1  (64 rows each)
    const int wn   = wid & 3;         // 0..3  (32 cols each)

    const int n_tiles = NT / BN;                       // 32
    const int m0 = (int)(blockIdx.x >> 5) * BM;        // n-fast rasterization
    const int n0 = (int)(blockIdx.x & (n_tiles - 1)) * BN;

    const uint32_t smem = smem_u32(dynsmem);
    const uint32_t smem_last = smem + (NSTAGES - 1) * STAGE_BYTES;

    for (int i = tid; i < BN; i += THREADS) bias_s[i] = bias[n0 + i];

    // ---- copy assignment: coalesced lane mapping, constant-folded addresses ----
    const int rowq = tid >> 3;                               // 0..31
    const uint32_t ch = (uint32_t)((tid & 7) << 4);          // 0..112
    const uint32_t chs = ch ^ (uint32_t)((rowq & 7) << 4);   // swizzle folded
    const uint8_t* gA = g_Xq + (size_t)(m0 + rowq) * KT + ch;
    const uint8_t* gB = g_Wq + (size_t)(n0 + rowq) * KT + ch;
    const uint32_t sAoff = (uint32_t)(rowq * BK) + chs;
    const uint32_t sBoff = (uint32_t)(A_BYTES + rowq * BK) + chs;

    auto issue_stage = [&](uint32_t sbase, const uint8_t* ga, const uint8_t* gb) {
        #pragma unroll
        for (int i = 0; i < 4; ++i) {
            cp_async16(sbase + sAoff + i * 4096, ga + (size_t)i * 32 * KT);
            cp_async16(sbase + sBoff + i * 4096, gb + (size_t)i * 32 * KT);
        }
    };

    // ---- prologue: fill stages 0..2 (3 groups in flight) ----
    #pragma unroll
    for (int s = 0; s < NSTAGES - 1; ++s) {
        issue_stage(smem + s * STAGE_BYTES, gA + s * BK, gB + s * BK);
        cp_commit();
    }

    // ---- per-lane ldmatrix offsets ----
    const int a_row_l = (lane & 15);
    const uint32_t a_kchunk = (uint32_t)((lane >> 4) << 4);
    const int b_row_l = ((lane >> 4) << 3) + (lane & 7);
    const uint32_t b_kchunk = (uint32_t)(((lane >> 3) & 1) << 4);

    uint32_t a_base[4], b_base[2];
    uint32_t koA[4], koB[4];
    {
        const uint32_t a_xor = (uint32_t)(((wm * 64 + a_row_l) & 7) << 4);
        const uint32_t b_xor = (uint32_t)(((wn * 32 + b_row_l) & 7) << 4);
        #pragma unroll
        for (int am = 0; am < 4; ++am)
            a_base[am] = (uint32_t)((wm * 64 + am * 16 + a_row_l) * BK);
        #pragma unroll
        for (int bp = 0; bp < 2; ++bp)
            b_base[bp] = (uint32_t)((wn * 32 + bp * 16 + b_row_l) * BK + A_BYTES);
        #pragma unroll
        for (int k = 0; k < 4; ++k) {
            koA[k] = ((uint32_t)(k * 32) + a_kchunk) ^ a_xor;
            koB[k] = ((uint32_t)(k * 32) + b_kchunk) ^ b_xor;
        }
    }

    float acc[4][4][4];
    #pragma unroll
    for (int i = 0; i < 4; ++i)
        #pragma unroll
        for (int j = 0; j < 4; ++j)
            #pragma unroll
            for (int k = 0; k < 4; ++k) acc[i][j][k] = 0.0f;

    uint32_t af[2][4][4];   // double-buffered A fragments
    uint32_t bf[2][2][4];   // double-buffered B fragments

    auto load_frags = [&](int buf, uint32_t base, int ka) {
        #pragma unroll
        for (int am = 0; am < 4; ++am)
            ldsm_x4(af[buf][am][0], af[buf][am][1], af[buf][am][2], af[buf][am][3],
                    base + a_base[am] + koA[ka]);
        #pragma unroll
        for (int bp = 0; bp < 2; ++bp)
            ldsm_x4(bf[buf][bp][0], bf[buf][bp][1], bf[buf][bp][2], bf[buf][bp][3],
                    base + b_base[bp] + koB[ka]);
    };
    auto mma_frags = [&](int buf) {
        #pragma unroll
        for (int am = 0; am < 4; ++am) {
            #pragma unroll
            for (int an = 0; an < 4; ++an) {
                const int bp = an >> 1;
                const int hl = (an & 1) << 1;
                mma_e4m3(acc[am][an][0], acc[am][an][1], acc[am][an][2], acc[am][an][3],
                         af[buf][am][0], af[buf][am][1], af[buf][am][2], af[buf][am][3],
                         bf[buf][bp][hl + 0], bf[buf][bp][hl + 1]);
            }
        }
    };

    // ---- wait for stage 0, prime fragment pipeline ----
    cp_wait<NSTAGES - 2>();
    __syncthreads();

    uint32_t cbase = smem;                           // stage being computed
    uint32_t nbase = smem + STAGE_BYTES;             // next stage
    uint32_t pbase = smem_last;                      // stage to fill
    const uint8_t* gnA = gA + (NSTAGES - 1) * BK;
    const uint8_t* gnB = gB + (NSTAGES - 1) * BK;

    load_frags(0, cbase, 0);

    for (int it = 0; it < K_ITERS; ++it) {
        #pragma unroll
        for (int ka = 0; ka < 4; ++ka) {
            const int cur = ka & 1, nxt = cur ^ 1;
            if (ka == 0) {
                if (it < K_ITERS - (NSTAGES - 1)) {
                    issue_stage(pbase, gnA, gnB);
                    gnA += BK;
                    gnB += BK;
                }
                cp_commit();   // unconditional: group counts stay aligned
                pbase = (pbase == smem_last) ? smem : pbase + STAGE_BYTES;
            }
            if (ka < 3) {
                load_frags(nxt, cbase, ka + 1);
            } else if (it < K_ITERS - 1) {
                cp_wait<NSTAGES - 2>();
                __syncthreads();
                load_frags(nxt, nbase, 0);   // post-barrier LDSM hides under ka=3 MMAs
            }
            mma_frags(cur);
        }
        cbase = nbase;
        nbase = (nbase == smem_last) ? smem : nbase + STAGE_BYTES;
    }

    // ---- epilogue: scale + bias + store ----
    const float sx = FP8MAX / fmaxf(in_amax[0], AMAX_EPS);
    const float sw = FP8MAX / fmaxf(w_amax[0], AMAX_EPS);
    const float inv = 1.0f / (sx * sw);

    const int row_base = m0 + wm * 64 + (lane >> 2);
    const int col_base = n0 + wn * 32 + (lane & 3) * 2;
    #pragma unroll
    for (int am = 0; am < 4; ++am) {
        #pragma unroll
        for (int an = 0; an < 4; ++an) {
            const int c = col_base + an * 8;
            const float b0 = bias_s[c - n0], b1 = bias_s[c - n0 + 1];
            const int r0 = row_base + am * 16;
            float2 v0 = make_float2(fmaf(acc[am][an][0], inv, b0),
                                    fmaf(acc[am][an][1], inv, b1));
            float2 v1 = make_float2(fmaf(acc[am][an][2], inv, b0),
                                    fmaf(acc[am][an][3], inv, b1));
            *(float2*)(out + (size_t)r0 * NT + c) = v0;
            *(float2*)(out + (size_t)(r0 + 8) * NT + c) = v1;
        }
    }

    // ---- fused amax EMA finalize (block 0, warp 0) ----
    if (blockIdx.x == 0 && wid == 0) {
        float mx = 0.0f, mw = 0.0f;
        for (int i = lane; i < QX_BLOCKS; i += 32) mx = fmaxf(mx, g_partX[i]);
        for (int i = lane; i < QW_BLOCKS; i += 32) mw = fmaxf(mw, g_partW[i]);
        #pragma unroll
        for (int o = 16; o > 0; o >>= 1) {
            mx = fmaxf(mx, __shfl_xor_sync(0xffffffffu, mx, o));
            mw = fmaxf(mw, __shfl_xor_sync(0xffffffffu, mw, o));
        }
        if (lane == 0) {
            out[out_size - 2] = fmaxf(fmaxf(in_amax[0] * MOMENTUM, mx), AMAX_EPS);
            out[out_size - 1] = fmaxf(fmaxf(w_amax[0] * MOMENTUM, mw), AMAX_EPS);
        }
    }
}

// ---------------- launch: 2 kernels ----------------
extern "C" void kernel_launch(void* const* d_in, const int* in_sizes, int n_in,
                              void* d_out, int out_size) {
    (void)in_sizes; (void)n_in;
    const float* x       = (const float*)d_in[0];
    const float* w       = (const float*)d_in[1];
    const float* bias    = (const float*)d_in[2];
    const float* in_amax = (const float*)d_in[3];
    const float* w_amax  = (const float*)d_in[4];
    float* out = (float*)d_out;

    quant_amax_kernel<<<Q_BLOCKS, 256>>>(x, w, in_amax, w_amax);

    cudaFuncSetAttribute(fp8_gemm_kernel,
                         cudaFuncAttributeMaxDynamicSharedMemorySize, DYN_SMEM);
    fp8_gemm_kernel<<<(MT / BM) * (NT / BN), THREADS, DYN_SMEM>>>(
        bias, in_amax, w_amax, out, out_size);
}

// round 13
// speedup vs baseline: 1.0302x; 1.0302x over previous
#include <cuda_runtime.h>
#include <cuda_fp8.h>
#include <cstdint>
#include <cstddef>

#define DI __device__ __forceinline__

// ---------------- problem constants ----------------
static constexpr int MT = 8192;   // tokens
static constexpr int NT = 4096;   // out features
static constexpr int KT = 4096;   // in features
static constexpr float FP8MAX = 448.0f;
static constexpr float AMAX_EPS = 1e-8f;
static constexpr float MOMENTUM = 0.95f;

// ---------------- GEMM tiling (R10 proven config) ----------------
static constexpr int BM = 128;
static constexpr int BN = 128;
static constexpr int BK = 128;                 // e4m3 bytes along K per stage
static constexpr int NSTAGES = 3;
static constexpr int K_ITERS = KT / BK;        // 32
static constexpr int A_BYTES = BM * BK;        // 16384
static constexpr int B_BYTES = BN * BK;        // 16384
static constexpr int STAGE_BYTES = A_BYTES + B_BYTES;   // 32768
static constexpr int DYN_SMEM = NSTAGES * STAGE_BYTES;  // 98304 -> 2 CTAs/SM
static constexpr int THREADS = 256;            // 8 warps: 2(m) x 4(n), warp 64x32

// quant grid split
static constexpr int QX_BLOCKS = 1024;
static constexpr int QW_BLOCKS = 512;
static constexpr int Q_BLOCKS  = QX_BLOCKS + QW_BLOCKS;   // 1536

// ---------------- scratch ----------------
__device__ __align__(128) uint8_t g_Xq[(size_t)MT * KT];
__device__ __align__(128) uint8_t g_Wq[(size_t)NT * KT];
__device__ float g_partX[QX_BLOCKS];
__device__ float g_partW[QW_BLOCKS];

// ---------------- PTX helpers (base sm_103 target ONLY) ----------------
DI uint32_t smem_u32(const void* p) {
    uint32_t a;
    asm("{ .reg .u64 t; cvta.to.shared.u64 t, %1; cvt.u32.u64 %0, t; }" : "=r"(a) : "l"(p));
    return a;
}
DI void cp_async16(uint32_t s, const void* g) {
    asm volatile("cp.async.cg.shared.global [%0], [%1], 16;" :: "r"(s), "l"(g) : "memory");
}
DI void cp_commit() { asm volatile("cp.async.commit_group;" ::: "memory"); }
template <int N> DI void cp_wait() {
    asm volatile("cp.async.wait_group %0;" :: "n"(N) : "memory");
}
DI void ldsm_x4(uint32_t& r0, uint32_t& r1, uint32_t& r2, uint32_t& r3, uint32_t addr) {
    asm volatile("ldmatrix.sync.aligned.m8n8.x4.shared.b16 {%0,%1,%2,%3}, [%4];"
                 : "=r"(r0), "=r"(r1), "=r"(r2), "=r"(r3) : "r"(addr));
}
DI void mma_e4m3(float& c0, float& c1, float& c2, float& c3,
                 uint32_t a0, uint32_t a1, uint32_t a2, uint32_t a3,
                 uint32_t b0, uint32_t b1) {
    asm volatile(
        "mma.sync.aligned.m16n8k32.row.col.f32.e4m3.e4m3.f32 "
        "{%0,%1,%2,%3}, {%4,%5,%6,%7}, {%8,%9}, {%0,%1,%2,%3};"
        : "+f"(c0), "+f"(c1), "+f"(c2), "+f"(c3)
        : "r"(a0), "r"(a1), "r"(a2), "r"(a3), "r"(b0), "r"(b1));
}
// pack two scaled floats into e4m3x2 (lo = first arg)
DI uint32_t cvt_e4m3x2(float lo, float hi) {
    uint16_t r;
    asm("cvt.rn.satfinite.e4m3x2.f32 %0, %1, %2;" : "=h"(r) : "f"(hi), "f"(lo));
    return (uint32_t)r;
}

// ---------------- kernel 1: combined quantize X + W, per-block absmax ----------------
__global__ void quant_amax_kernel(const float* __restrict__ x,
                                  const float* __restrict__ w,
                                  const float* __restrict__ in_amax,
                                  const float* __restrict__ w_amax) {
    __shared__ float smax[8];
    const bool isX = (blockIdx.x < QX_BLOCKS);
    const int bid  = isX ? (int)blockIdx.x : (int)blockIdx.x - QX_BLOCKS;
    const int nblk = isX ? QX_BLOCKS : QW_BLOCKS;
    const int n4   = isX ? MT * KT / 4 : NT * KT / 4;
    const float4* src4 = (const float4*)(isX ? x : w);
    uint32_t* dst4 = (uint32_t*)(isX ? g_Xq : g_Wq);
    const float s = FP8MAX / fmaxf((isX ? in_amax : w_amax)[0], AMAX_EPS);

    float lmax = 0.0f;
    for (int i = bid * blockDim.x + threadIdx.x; i < n4; i += nblk * blockDim.x) {
        float4 v = src4[i];
        lmax = fmaxf(lmax, fmaxf(fmaxf(fabsf(v.x), fabsf(v.y)), fmaxf(fabsf(v.z), fabsf(v.w))));
        const uint32_t lo = cvt_e4m3x2(v.x * s, v.y * s);
        const uint32_t hi = cvt_e4m3x2(v.z * s, v.w * s);
        dst4[i] = lo | (hi << 16);
    }
    #pragma unroll
    for (int o = 16; o > 0; o >>= 1) lmax = fmaxf(lmax, __shfl_xor_sync(0xffffffffu, lmax, o));
    if ((threadIdx.x & 31) == 0) smax[threadIdx.x >> 5] = lmax;
    __syncthreads();
    if (threadIdx.x == 0) {
        float b = smax[0];
        #pragma unroll
        for (int ww = 1; ww < 8; ++ww) b = fmaxf(b, smax[ww]);
        (isX ? g_partX : g_partW)[bid] = b;
    }
}

// ---------------- kernel 2: fp8 GEMM, barrier every 2 iterations ----------------
__global__ void __launch_bounds__(THREADS, 2) fp8_gemm_kernel(
    const float* __restrict__ bias,
    const float* __restrict__ in_amax,
    const float* __restrict__ w_amax,
    float* __restrict__ out, int out_size)
{
    extern __shared__ uint8_t dynsmem[];
    __shared__ float bias_s[BN];

    const int tid  = threadIdx.x;
    const int wid  = tid >> 5;
    const int lane = tid & 31;
    const int wm   = wid >> 2;        // 0..1  (64 rows each)
    const int wn   = wid & 3;         // 0..3  (32 cols each)

    const int n_tiles = NT / BN;                       // 32
    const int m0 = (int)(blockIdx.x >> 5) * BM;        // n-fast rasterization
    const int n0 = (int)(blockIdx.x & (n_tiles - 1)) * BN;

    const uint32_t smem = smem_u32(dynsmem);
    const uint32_t smem_last = smem + (NSTAGES - 1) * STAGE_BYTES;

    for (int i = tid; i < BN; i += THREADS) bias_s[i] = bias[n0 + i];

    // ---- copy assignment: coalesced lane mapping, constant-folded addresses ----
    const int rowq = tid >> 3;                               // 0..31
    const uint32_t ch = (uint32_t)((tid & 7) << 4);          // 0..112
    const uint32_t chs = ch ^ (uint32_t)((rowq & 7) << 4);   // swizzle folded
    const uint8_t* gA = g_Xq + (size_t)(m0 + rowq) * KT + ch;
    const uint8_t* gB = g_Wq + (size_t)(n0 + rowq) * KT + ch;
    const uint32_t sAoff = (uint32_t)(rowq * BK) + chs;
    const uint32_t sBoff = (uint32_t)(A_BYTES + rowq * BK) + chs;

    auto issue_stage = [&](uint32_t sbase, const uint8_t* ga, const uint8_t* gb) {
        #pragma unroll
        for (int i = 0; i < 4; ++i) {
            cp_async16(sbase + sAoff + i * 4096, ga + (size_t)i * 32 * KT);
            cp_async16(sbase + sBoff + i * 4096, gb + (size_t)i * 32 * KT);
        }
    };

    // ---- prologue: fill stage 0 only (prefetch distance 1) ----
    issue_stage(smem, gA, gB);
    cp_commit();

    // ---- per-lane ldmatrix offsets ----
    const int a_row_l = (lane & 15);
    const uint32_t a_kchunk = (uint32_t)((lane >> 4) << 4);
    const int b_row_l = ((lane >> 4) << 3) + (lane & 7);
    const uint32_t b_kchunk = (uint32_t)(((lane >> 3) & 1) << 4);

    uint32_t a_base[4], b_base[2];
    uint32_t a_xor, b_xor;
    {
        #pragma unroll
        for (int am = 0; am < 4; ++am)
            a_base[am] = (uint32_t)((wm * 64 + am * 16 + a_row_l) * BK);
        a_xor = (uint32_t)(((wm * 64 + a_row_l) & 7) << 4);
        #pragma unroll
        for (int bp = 0; bp < 2; ++bp)
            b_base[bp] = (uint32_t)((wn * 32 + bp * 16 + b_row_l) * BK + A_BYTES);
        b_xor = (uint32_t)(((wn * 32 + b_row_l) & 7) << 4);
    }

    float acc[4][4][4];
    #pragma unroll
    for (int i = 0; i < 4; ++i)
        #pragma unroll
        for (int j = 0; j < 4; ++j)
            #pragma unroll
            for (int k = 0; k < 4; ++k) acc[i][j][k] = 0.0f;

    // one ka-step of compute (6 LDSM + 16 QMMA)
    auto compute_ka = [&](uint32_t cbase, int ka) {
        const uint32_t koffA = ((uint32_t)(ka * 32) + a_kchunk) ^ a_xor;
        const uint32_t koffB = ((uint32_t)(ka * 32) + b_kchunk) ^ b_xor;
        uint32_t af[4][4];
        #pragma unroll
        for (int am = 0; am < 4; ++am)
            ldsm_x4(af[am][0], af[am][1], af[am][2], af[am][3],
                    cbase + a_base[am] + koffA);
        uint32_t bf[2][4];
        #pragma unroll
        for (int bp = 0; bp < 2; ++bp)
            ldsm_x4(bf[bp][0], bf[bp][1], bf[bp][2], bf[bp][3],
                    cbase + b_base[bp] + koffB);
        #pragma unroll
        for (int am = 0; am < 4; ++am) {
            #pragma unroll
            for (int an = 0; an < 4; ++an) {
                const int bp = an >> 1;
                const int hl = (an & 1) << 1;
                mma_e4m3(acc[am][an][0], acc[am][an][1], acc[am][an][2], acc[am][an][3],
                         af[am][0], af[am][1], af[am][2], af[am][3],
                         bf[bp][hl + 0], bf[bp][hl + 1]);
            }
        }
    };

    // ---- main loop: distance-1 prefetch, barrier every OTHER iteration ----
    // WAR safety: fill target (it+1)%3 was last read at it-2; a barrier at every
    // even-iteration start separates that read from this write for both parities.
    uint32_t cbase = smem;                       // stage being computed (it % 3)
    uint32_t pbase = smem + STAGE_BYTES;         // stage being filled ((it+1) % 3)
    const uint8_t* gnA = gA + BK;
    const uint8_t* gnB = gB + BK;

    for (int it = 0; it < K_ITERS; ++it) {
        cp_wait<0>();                            // current stage data ready (per-warp)
        if ((it & 1) == 0) __syncthreads();      // WAR guard, every 2 iterations

        compute_ka(cbase, 0);

        // fill stage it+1 under the tensor shadow
        if (it < K_ITERS - 1) {
            issue_stage(pbase, gnA, gnB);
            gnA += BK;
            gnB += BK;
        }
        cp_commit();                             // unconditional: group counts aligned
        pbase = (pbase == smem_last) ? smem : pbase + STAGE_BYTES;

        compute_ka(cbase, 1);
        compute_ka(cbase, 2);
        compute_ka(cbase, 3);
        cbase = (cbase == smem_last) ? smem : cbase + STAGE_BYTES;
    }

    // ---- epilogue: scale + bias + store ----
    const float sx = FP8MAX / fmaxf(in_amax[0], AMAX_EPS);
    const float sw = FP8MAX / fmaxf(w_amax[0], AMAX_EPS);
    const float inv = 1.0f / (sx * sw);

    const int row_base = m0 + wm * 64 + (lane >> 2);
    const int col_base = n0 + wn * 32 + (lane & 3) * 2;
    #pragma unroll
    for (int am = 0; am < 4; ++am) {
        #pragma unroll
        for (int an = 0; an < 4; ++an) {
            const int c = col_base + an * 8;
            const float b0 = bias_s[c - n0], b1 = bias_s[c - n0 + 1];
            const int r0 = row_base + am * 16;
            float2 v0 = make_float2(fmaf(acc[am][an][0], inv, b0),
                                    fmaf(acc[am][an][1], inv, b1));
            float2 v1 = make_float2(fmaf(acc[am][an][2], inv, b0),
                                    fmaf(acc[am][an][3], inv, b1));
            *(float2*)(out + (size_t)r0 * NT + c) = v0;
            *(float2*)(out + (size_t)(r0 + 8) * NT + c) = v1;
        }
    }

    // ---- fused amax EMA finalize (block 0, warp 0) ----
    if (blockIdx.x == 0 && wid == 0) {
        float mx = 0.0f, mw = 0.0f;
        for (int i = lane; i < QX_BLOCKS; i += 32) mx = fmaxf(mx, g_partX[i]);
        for (int i = lane; i < QW_BLOCKS; i += 32) mw = fmaxf(mw, g_partW[i]);
        #pragma unroll
        for (int o = 16; o > 0; o >>= 1) {
            mx = fmaxf(mx, __shfl_xor_sync(0xffffffffu, mx, o));
            mw = fmaxf(mw, __shfl_xor_sync(0xffffffffu, mw, o));
        }
        if (lane == 0) {
            out[out_size - 2] = fmaxf(fmaxf(in_amax[0] * MOMENTUM, mx), AMAX_EPS);
            out[out_size - 1] = fmaxf(fmaxf(w_amax[0] * MOMENTUM, mw), AMAX_EPS);
        }
    }
}

// ---------------- launch: 2 kernels ----------------
extern "C" void kernel_launch(void* const* d_in, const int* in_sizes, int n_in,
                              void* d_out, int out_size) {
    (void)in_sizes; (void)n_in;
    const float* x       = (const float*)d_in[0];
    const float* w       = (const float*)d_in[1];
    const float* bias    = (const float*)d_in[2];
    const float* in_amax = (const float*)d_in[3];
    const float* w_amax  = (const float*)d_in[4];
    float* out = (float*)d_out;

    quant_amax_kernel<<<Q_BLOCKS, 256>>>(x, w, in_amax, w_amax);

    cudaFuncSetAttribute(fp8_gemm_kernel,
                         cudaFuncAttributeMaxDynamicSharedMemorySize, DYN_SMEM);
    fp8_gemm_kernel<<<(MT / BM) * (NT / BN), THREADS, DYN_SMEM>>>(
        bias, in_amax, w_amax, out, out_size);
}

// round 14
// speedup vs baseline: 1.0397x; 1.0092x over previous
#include <cuda_runtime.h>
#include <cuda_fp8.h>
#include <cstdint>
#include <cstddef>

#define DI __device__ __forceinline__

// ---------------- problem constants ----------------
static constexpr int MT = 8192;   // tokens
static constexpr int NT = 4096;   // out features
static constexpr int KT = 4096;   // in features
static constexpr float FP8MAX = 448.0f;
static constexpr float AMAX_EPS = 1e-8f;
static constexpr float MOMENTUM = 0.95f;

// ---------------- GEMM tiling (R10 proven config) ----------------
static constexpr int BM = 128;
static constexpr int BN = 128;
static constexpr int BK = 128;                 // e4m3 bytes along K per stage
static constexpr int NSTAGES = 3;
static constexpr int K_ITERS = KT / BK;        // 32
static constexpr int A_BYTES = BM * BK;        // 16384
static constexpr int B_BYTES = BN * BK;        // 16384
static constexpr int STAGE_BYTES = A_BYTES + B_BYTES;   // 32768
static constexpr int DYN_SMEM = NSTAGES * STAGE_BYTES;  // 98304 -> 2 CTAs/SM
static constexpr int THREADS = 256;            // 8 warps: 2(m) x 4(n), warp 64x32

// quant grid split
static constexpr int QX_BLOCKS = 1024;
static constexpr int QW_BLOCKS = 512;
static constexpr int Q_BLOCKS  = QX_BLOCKS + QW_BLOCKS;   // 1536

// ---------------- scratch ----------------
__device__ __align__(128) uint8_t g_Xq[(size_t)MT * KT];
__device__ __align__(128) uint8_t g_Wq[(size_t)NT * KT];
__device__ float g_partX[QX_BLOCKS];
__device__ float g_partW[QW_BLOCKS];

// ---------------- PTX helpers (base sm_103 target ONLY) ----------------
DI uint32_t smem_u32(const void* p) {
    uint32_t a;
    asm("{ .reg .u64 t; cvta.to.shared.u64 t, %1; cvt.u32.u64 %0, t; }" : "=r"(a) : "l"(p));
    return a;
}
DI void cp_async16(uint32_t s, const void* g) {
    asm volatile("cp.async.cg.shared.global [%0], [%1], 16;" :: "r"(s), "l"(g) : "memory");
}
DI void cp_commit() { asm volatile("cp.async.commit_group;" ::: "memory"); }
template <int N> DI void cp_wait() {
    asm volatile("cp.async.wait_group %0;" :: "n"(N) : "memory");
}
DI void ldsm_x4(uint32_t& r0, uint32_t& r1, uint32_t& r2, uint32_t& r3, uint32_t addr) {
    asm volatile("ldmatrix.sync.aligned.m8n8.x4.shared.b16 {%0,%1,%2,%3}, [%4];"
                 : "=r"(r0), "=r"(r1), "=r"(r2), "=r"(r3) : "r"(addr));
}
DI void mma_e4m3(float& c0, float& c1, float& c2, float& c3,
                 uint32_t a0, uint32_t a1, uint32_t a2, uint32_t a3,
                 uint32_t b0, uint32_t b1) {
    asm volatile(
        "mma.sync.aligned.m16n8k32.row.col.f32.e4m3.e4m3.f32 "
        "{%0,%1,%2,%3}, {%4,%5,%6,%7}, {%8,%9}, {%0,%1,%2,%3};"
        : "+f"(c0), "+f"(c1), "+f"(c2), "+f"(c3)
        : "r"(a0), "r"(a1), "r"(a2), "r"(a3), "r"(b0), "r"(b1));
}
// pack two scaled floats into e4m3x2 (lo = first arg)
DI uint32_t cvt_e4m3x2(float lo, float hi) {
    uint16_t r;
    asm("cvt.rn.satfinite.e4m3x2.f32 %0, %1, %2;" : "=h"(r) : "f"(hi), "f"(lo));
    return (uint32_t)r;
}

// ---------------- kernel 1: combined quantize X + W, 64B/thread, per-block absmax ----------------
__global__ void quant_amax_kernel(const float* __restrict__ x,
                                  const float* __restrict__ w,
                                  const float* __restrict__ in_amax,
                                  const float* __restrict__ w_amax) {
    __shared__ float smax[8];
    const bool isX = (blockIdx.x < QX_BLOCKS);
    const int bid  = isX ? (int)blockIdx.x : (int)blockIdx.x - QX_BLOCKS;
    const int nthr = (isX ? QX_BLOCKS : QW_BLOCKS) * 256;
    const int ngrp = (isX ? MT * KT : NT * KT) / 16;   // groups of 16 floats (64B)
    const float4* src4 = (const float4*)(isX ? x : w);
    uint4* dst16 = (uint4*)(isX ? g_Xq : g_Wq);
    const float s = FP8MAX / fmaxf((isX ? in_amax : w_amax)[0], AMAX_EPS);

    float lmax = 0.0f;
    for (int g = bid * 256 + (int)threadIdx.x; g < ngrp; g += nthr) {
        const float4 v0 = src4[g * 4 + 0];
        const float4 v1 = src4[g * 4 + 1];
        const float4 v2 = src4[g * 4 + 2];
        const float4 v3 = src4[g * 4 + 3];
        float m01 = fmaxf(fmaxf(fabsf(v0.x), fabsf(v0.y)), fmaxf(fabsf(v0.z), fabsf(v0.w)));
        m01 = fmaxf(m01, fmaxf(fmaxf(fabsf(v1.x), fabsf(v1.y)), fmaxf(fabsf(v1.z), fabsf(v1.w))));
        float m23 = fmaxf(fmaxf(fabsf(v2.x), fabsf(v2.y)), fmaxf(fabsf(v2.z), fabsf(v2.w)));
        m23 = fmaxf(m23, fmaxf(fmaxf(fabsf(v3.x), fabsf(v3.y)), fmaxf(fabsf(v3.z), fabsf(v3.w))));
        lmax = fmaxf(lmax, fmaxf(m01, m23));
        uint4 o;
        o.x = cvt_e4m3x2(v0.x * s, v0.y * s) | (cvt_e4m3x2(v0.z * s, v0.w * s) << 16);
        o.y = cvt_e4m3x2(v1.x * s, v1.y * s) | (cvt_e4m3x2(v1.z * s, v1.w * s) << 16);
        o.z = cvt_e4m3x2(v2.x * s, v2.y * s) | (cvt_e4m3x2(v2.z * s, v2.w * s) << 16);
        o.w = cvt_e4m3x2(v3.x * s, v3.y * s) | (cvt_e4m3x2(v3.z * s, v3.w * s) << 16);
        dst16[g] = o;
    }
    #pragma unroll
    for (int o = 16; o > 0; o >>= 1) lmax = fmaxf(lmax, __shfl_xor_sync(0xffffffffu, lmax, o));
    if ((threadIdx.x & 31) == 0) smax[threadIdx.x >> 5] = lmax;
    __syncthreads();
    if (threadIdx.x == 0) {
        float b = smax[0];
        #pragma unroll
        for (int ww = 1; ww < 8; ++ww) b = fmaxf(b, smax[ww]);
        (isX ? g_partX : g_partW)[bid] = b;
    }
}

// ---------------- kernel 2: fp8 GEMM (R10) + warp-phase-staggered ka order ----------------
__global__ void __launch_bounds__(THREADS, 2) fp8_gemm_kernel(
    const float* __restrict__ bias,
    const float* __restrict__ in_amax,
    const float* __restrict__ w_amax,
    float* __restrict__ out, int out_size)
{
    extern __shared__ uint8_t dynsmem[];
    __shared__ float bias_s[BN];

    const int tid  = threadIdx.x;
    const int wid  = tid >> 5;
    const int lane = tid & 31;
    const int wm   = wid >> 2;        // 0..1  (64 rows each)
    const int wn   = wid & 3;         // 0..3  (32 cols each)

    const int n_tiles = NT / BN;                       // 32
    const int m0 = (int)(blockIdx.x >> 5) * BM;        // n-fast rasterization
    const int n0 = (int)(blockIdx.x & (n_tiles - 1)) * BN;

    const uint32_t smem = smem_u32(dynsmem);
    const uint32_t smem_last = smem + (NSTAGES - 1) * STAGE_BYTES;

    for (int i = tid; i < BN; i += THREADS) bias_s[i] = bias[n0 + i];

    // ---- copy assignment: coalesced lane mapping, constant-folded addresses ----
    const int rowq = tid >> 3;                               // 0..31
    const uint32_t ch = (uint32_t)((tid & 7) << 4);          // 0..112
    const uint32_t chs = ch ^ (uint32_t)((rowq & 7) << 4);   // swizzle folded
    const uint8_t* gA = g_Xq + (size_t)(m0 + rowq) * KT + ch;
    const uint8_t* gB = g_Wq + (size_t)(n0 + rowq) * KT + ch;
    const uint32_t sAoff = (uint32_t)(rowq * BK) + chs;
    const uint32_t sBoff = (uint32_t)(A_BYTES + rowq * BK) + chs;

    auto issue_stage = [&](uint32_t sbase, const uint8_t* ga, const uint8_t* gb) {
        #pragma unroll
        for (int i = 0; i < 4; ++i) {
            cp_async16(sbase + sAoff + i * 4096, ga + (size_t)i * 32 * KT);
            cp_async16(sbase + sBoff + i * 4096, gb + (size_t)i * 32 * KT);
        }
    };

    // ---- prologue: stages 0..NSTAGES-2 ----
    #pragma unroll
    for (int s = 0; s < NSTAGES - 1; ++s) {
        issue_stage(smem + s * STAGE_BYTES, gA + s * BK, gB + s * BK);
        cp_commit();
    }

    // ---- per-lane ldmatrix offsets, ka order staggered by warp group ----
    const int a_row_l = (lane & 15);
    const uint32_t a_kchunk = (uint32_t)((lane >> 4) << 4);
    const int b_row_l = ((lane >> 4) << 3) + (lane & 7);
    const uint32_t b_kchunk = (uint32_t)(((lane >> 3) & 1) << 4);
    const int kao = (wid & 4) ? 2 : 0;   // warps 4-7 start at ka=2

    uint32_t a_base[4], b_base[2];
    uint32_t koAp[4], koBp[4];           // permuted K-offsets: slot j -> ka (kao+j)&3
    {
        const uint32_t a_xor = (uint32_t)(((wm * 64 + a_row_l) & 7) << 4);
        const uint32_t b_xor = (uint32_t)(((wn * 32 + b_row_l) & 7) << 4);
        #pragma unroll
        for (int am = 0; am < 4; ++am)
            a_base[am] = (uint32_t)((wm * 64 + am * 16 + a_row_l) * BK);
        #pragma unroll
        for (int bp = 0; bp < 2; ++bp)
            b_base[bp] = (uint32_t)((wn * 32 + bp * 16 + b_row_l) * BK + A_BYTES);
        #pragma unroll
        for (int j = 0; j < 4; ++j) {
            const int kk = (kao + j) & 3;
            koAp[j] = ((uint32_t)(kk * 32) + a_kchunk) ^ a_xor;
            koBp[j] = ((uint32_t)(kk * 32) + b_kchunk) ^ b_xor;
        }
    }

    float acc[4][4][4];
    #pragma unroll
    for (int i = 0; i < 4; ++i)
        #pragma unroll
        for (int j = 0; j < 4; ++j)
            #pragma unroll
            for (int k = 0; k < 4; ++k) acc[i][j][k] = 0.0f;

    // one ka-slot of compute (6 LDSM + 16 QMMA); slot j maps to ka (kao+j)&3
    auto compute_slot = [&](uint32_t cbase, int j) {
        uint32_t af[4][4];
        #pragma unroll
        for (int am = 0; am < 4; ++am)
            ldsm_x4(af[am][0], af[am][1], af[am][2], af[am][3],
                    cbase + a_base[am] + koAp[j]);
        uint32_t bf[2][4];
        #pragma unroll
        for (int bp = 0; bp < 2; ++bp)
            ldsm_x4(bf[bp][0], bf[bp][1], bf[bp][2], bf[bp][3],
                    cbase + b_base[bp] + koBp[j]);
        #pragma unroll
        for (int am = 0; am < 4; ++am) {
            #pragma unroll
            for (int an = 0; an < 4; ++an) {
                const int bp = an >> 1;
                const int hl = (an & 1) << 1;
                mma_e4m3(acc[am][an][0], acc[am][an][1], acc[am][an][2], acc[am][an][3],
                         af[am][0], af[am][1], af[am][2], af[am][3],
                         bf[bp][hl + 0], bf[bp][hl + 1]);
            }
        }
    };

    // ---- main loop: R10 structure (distance-2 prefetch, sync every iter) ----
    uint32_t cbase = smem;                       // compute stage base
    uint32_t pbase = smem_last;                  // produce stage base
    const uint8_t* gnA = gA + (NSTAGES - 1) * BK;
    const uint8_t* gnB = gB + (NSTAGES - 1) * BK;

    for (int it = 0; it < K_ITERS; ++it) {
        cp_wait<NSTAGES - 2>();
        __syncthreads();

        compute_slot(cbase, 0);

        // issue next-stage copies under the tensor shadow
        if (it < K_ITERS - (NSTAGES - 1)) {
            issue_stage(pbase, gnA, gnB);
            gnA += BK;
            gnB += BK;
        }
        cp_commit();    // unconditional: keeps wait_group counts aligned
        pbase = (pbase == smem_last) ? smem : pbase + STAGE_BYTES;

        compute_slot(cbase, 1);
        compute_slot(cbase, 2);
        compute_slot(cbase, 3);
        cbase = (cbase == smem_last) ? smem : cbase + STAGE_BYTES;
    }

    // ---- epilogue: scale + bias + store ----
    const float sx = FP8MAX / fmaxf(in_amax[0], AMAX_EPS);
    const float sw = FP8MAX / fmaxf(w_amax[0], AMAX_EPS);
    const float inv = 1.0f / (sx * sw);

    const int row_base = m0 + wm * 64 + (lane >> 2);
    const int col_base = n0 + wn * 32 + (lane & 3) * 2;
    #pragma unroll
    for (int am = 0; am < 4; ++am) {
        #pragma unroll
        for (int an = 0; an < 4; ++an) {
            const int c = col_base + an * 8;
            const float b0 = bias_s[c - n0], b1 = bias_s[c - n0 + 1];
            const int r0 = row_base + am * 16;
            float2 v0 = make_float2(fmaf(acc[am][an][0], inv, b0),
                                    fmaf(acc[am][an][1], inv, b1));
            float2 v1 = make_float2(fmaf(acc[am][an][2], inv, b0),
                                    fmaf(acc[am][an][3], inv, b1));
            *(float2*)(out + (size_t)r0 * NT + c) = v0;
            *(float2*)(out + (size_t)(r0 + 8) * NT + c) = v1;
        }
    }

    // ---- fused amax EMA finalize (block 0, warp 0) ----
    if (blockIdx.x == 0 && wid == 0) {
        float mx = 0.0f, mw = 0.0f;
        for (int i = lane; i < QX_BLOCKS; i += 32) mx = fmaxf(mx, g_partX[i]);
        for (int i = lane; i < QW_BLOCKS; i += 32) mw = fmaxf(mw, g_partW[i]);
        #pragma unroll
        for (int o = 16; o > 0; o >>= 1) {
            mx = fmaxf(mx, __shfl_xor_sync(0xffffffffu, mx, o));
            mw = fmaxf(mw, __shfl_xor_sync(0xffffffffu, mw, o));
        }
        if (lane == 0) {
            out[out_size - 2] = fmaxf(fmaxf(in_amax[0] * MOMENTUM, mx), AMAX_EPS);
            out[out_size - 1] = fmaxf(fmaxf(w_amax[0] * MOMENTUM, mw), AMAX_EPS);
        }
    }
}

// ---------------- launch: 2 kernels ----------------
extern "C" void kernel_launch(void* const* d_in, const int* in_sizes, int n_in,
                              void* d_out, int out_size) {
    (void)in_sizes; (void)n_in;
    const float* x       = (const float*)d_in[0];
    const float* w       = (const float*)d_in[1];
    const float* bias    = (const float*)d_in[2];
    const float* in_amax = (const float*)d_in[3];
    const float* w_amax  = (const float*)d_in[4];
    float* out = (float*)d_out;

    quant_amax_kernel<<<Q_BLOCKS, 256>>>(x, w, in_amax, w_amax);

    cudaFuncSetAttribute(fp8_gemm_kernel,
                         cudaFuncAttributeMaxDynamicSharedMemorySize, DYN_SMEM);
    fp8_gemm_kernel<<<(MT / BM) * (NT / BN), THREADS, DYN_SMEM>>>(
        bias, in_amax, w_amax, out, out_size);
}

// round 15
// speedup vs baseline: 1.0716x; 1.0306x over previous
#include <cuda_runtime.h>
#include <cuda_fp8.h>
#include <cstdint>
#include <cstddef>

#define DI __device__ __forceinline__

// ---------------- problem constants ----------------
static constexpr int MT = 8192;   // tokens
static constexpr int NT = 4096;   // out features
static constexpr int KT = 4096;   // in features
static constexpr float FP8MAX = 448.0f;
static constexpr float AMAX_EPS = 1e-8f;
static constexpr float MOMENTUM = 0.95f;

// ---------------- GEMM tiling (proven config) ----------------
static constexpr int BM = 128;
static constexpr int BN = 128;
static constexpr int BK = 128;                 // e4m3 bytes along K per stage
static constexpr int NSTAGES = 3;
static constexpr int K_ITERS = KT / BK;        // 32
static constexpr int A_BYTES = BM * BK;        // 16384
static constexpr int B_BYTES = BN * BK;        // 16384
static constexpr int STAGE_BYTES = A_BYTES + B_BYTES;   // 32768
static constexpr int DYN_SMEM = NSTAGES * STAGE_BYTES;  // 98304 -> 2 CTAs/SM
static constexpr int THREADS = 256;            // 8 warps: 2(m) x 4(n), warp 64x32

// quant grid split
static constexpr int QX_BLOCKS = 1024;
static constexpr int QW_BLOCKS = 512;
static constexpr int Q_BLOCKS  = QX_BLOCKS + QW_BLOCKS;   // 1536

// ---------------- scratch ----------------
__device__ __align__(128) uint8_t g_Xq[(size_t)MT * KT];
__device__ __align__(128) uint8_t g_Wq[(size_t)NT * KT];
__device__ unsigned g_amax_bits[2];   // zero-init; reset by last quant block each run
__device__ int g_qdone;               // zero-init; reset by last quant block each run

// ---------------- PTX helpers (base sm_103 target ONLY) ----------------
DI uint32_t smem_u32(const void* p) {
    uint32_t a;
    asm("{ .reg .u64 t; cvta.to.shared.u64 t, %1; cvt.u32.u64 %0, t; }" : "=r"(a) : "l"(p));
    return a;
}
DI void cp_async16(uint32_t s, const void* g) {
    asm volatile("cp.async.cg.shared.global [%0], [%1], 16;" :: "r"(s), "l"(g) : "memory");
}
DI void cp_commit() { asm volatile("cp.async.commit_group;" ::: "memory"); }
template <int N> DI void cp_wait() {
    asm volatile("cp.async.wait_group %0;" :: "n"(N) : "memory");
}
DI void ldsm_x4(uint32_t& r0, uint32_t& r1, uint32_t& r2, uint32_t& r3, uint32_t addr) {
    asm volatile("ldmatrix.sync.aligned.m8n8.x4.shared.b16 {%0,%1,%2,%3}, [%4];"
                 : "=r"(r0), "=r"(r1), "=r"(r2), "=r"(r3) : "r"(addr));
}
DI void mma_e4m3(float& c0, float& c1, float& c2, float& c3,
                 uint32_t a0, uint32_t a1, uint32_t a2, uint32_t a3,
                 uint32_t b0, uint32_t b1) {
    asm volatile(
        "mma.sync.aligned.m16n8k32.row.col.f32.e4m3.e4m3.f32 "
        "{%0,%1,%2,%3}, {%4,%5,%6,%7}, {%8,%9}, {%0,%1,%2,%3};"
        : "+f"(c0), "+f"(c1), "+f"(c2), "+f"(c3)
        : "r"(a0), "r"(a1), "r"(a2), "r"(a3), "r"(b0), "r"(b1));
}
DI uint32_t cvt_e4m3x2(float lo, float hi) {
    uint16_t r;
    asm("cvt.rn.satfinite.e4m3x2.f32 %0, %1, %2;" : "=h"(r) : "f"(hi), "f"(lo));
    return (uint32_t)r;
}
DI void pdl_launch_dependents() {
    asm volatile("griddepcontrol.launch_dependents;" ::: "memory");
}
DI void pdl_wait() {
    asm volatile("griddepcontrol.wait;" ::: "memory");
}

// ---------------- kernel 1: quantize X + W, amax EMA finalize, PDL trigger ----------------
__global__ void quant_amax_kernel(const float* __restrict__ x,
                                  const float* __restrict__ w,
                                  const float* __restrict__ in_amax,
                                  const float* __restrict__ w_amax,
                                  float* __restrict__ out, int out_size) {
    __shared__ float smax[8];
    const bool isX = (blockIdx.x < QX_BLOCKS);
    const int bid  = isX ? (int)blockIdx.x : (int)blockIdx.x - QX_BLOCKS;
    const int nthr = (isX ? QX_BLOCKS : QW_BLOCKS) * 256;
    const int ngrp = (isX ? MT * KT : NT * KT) / 16;   // groups of 16 floats (64B)
    const float4* src4 = (const float4*)(isX ? x : w);
    uint4* dst16 = (uint4*)(isX ? g_Xq : g_Wq);
    const float s = FP8MAX / fmaxf((isX ? in_amax : w_amax)[0], AMAX_EPS);

    float lmax = 0.0f;
    for (int g = bid * 256 + (int)threadIdx.x; g < ngrp; g += nthr) {
        const float4 v0 = src4[g * 4 + 0];
        const float4 v1 = src4[g * 4 + 1];
        const float4 v2 = src4[g * 4 + 2];
        const float4 v3 = src4[g * 4 + 3];
        float m01 = fmaxf(fmaxf(fabsf(v0.x), fabsf(v0.y)), fmaxf(fabsf(v0.z), fabsf(v0.w)));
        m01 = fmaxf(m01, fmaxf(fmaxf(fabsf(v1.x), fabsf(v1.y)), fmaxf(fabsf(v1.z), fabsf(v1.w))));
        float m23 = fmaxf(fmaxf(fabsf(v2.x), fabsf(v2.y)), fmaxf(fabsf(v2.z), fabsf(v2.w)));
        m23 = fmaxf(m23, fmaxf(fmaxf(fabsf(v3.x), fabsf(v3.y)), fmaxf(fabsf(v3.z), fabsf(v3.w))));
        lmax = fmaxf(lmax, fmaxf(m01, m23));
        uint4 o;
        o.x = cvt_e4m3x2(v0.x * s, v0.y * s) | (cvt_e4m3x2(v0.z * s, v0.w * s) << 16);
        o.y = cvt_e4m3x2(v1.x * s, v1.y * s) | (cvt_e4m3x2(v1.z * s, v1.w * s) << 16);
        o.z = cvt_e4m3x2(v2.x * s, v2.y * s) | (cvt_e4m3x2(v2.z * s, v2.w * s) << 16);
        o.w = cvt_e4m3x2(v3.x * s, v3.y * s) | (cvt_e4m3x2(v3.z * s, v3.w * s) << 16);
        dst16[g] = o;
    }

    // All quantized data for this block is stored: allow the GEMM to launch.
    // (Everything below touches only g_amax_bits / g_qdone / out[-2:], which the
    //  GEMM never reads.)
    pdl_launch_dependents();

    // block absmax reduction
    #pragma unroll
    for (int o = 16; o > 0; o >>= 1) lmax = fmaxf(lmax, __shfl_xor_sync(0xffffffffu, lmax, o));
    if ((threadIdx.x & 31) == 0) smax[threadIdx.x >> 5] = lmax;
    __syncthreads();
    if (threadIdx.x == 0) {
        float b = smax[0];
        #pragma unroll
        for (int ww = 1; ww < 8; ++ww) b = fmaxf(b, smax[ww]);
        atomicMax(&g_amax_bits[isX ? 0 : 1], __float_as_uint(b));
        __threadfence();
        // last-finishing block computes the EMA outputs and resets state
        if (atomicAdd(&g_qdone, 1) == Q_BLOCKS - 1) {
            const float mx = __uint_as_float(g_amax_bits[0]);
            const float mw = __uint_as_float(g_amax_bits[1]);
            out[out_size - 2] = fmaxf(fmaxf(in_amax[0] * MOMENTUM, mx), AMAX_EPS);
            out[out_size - 1] = fmaxf(fmaxf(w_amax[0] * MOMENTUM, mw), AMAX_EPS);
            g_amax_bits[0] = 0u;
            g_amax_bits[1] = 0u;
            g_qdone = 0;
            __threadfence();
        }
    }
}

// ---------------- kernel 2: pure fp8 GEMM (PDL consumer) ----------------
__global__ void __launch_bounds__(THREADS, 2) fp8_gemm_kernel(
    const float* __restrict__ bias,
    const float* __restrict__ in_amax,
    const float* __restrict__ w_amax,
    float* __restrict__ out)
{
    extern __shared__ uint8_t dynsmem[];
    __shared__ float bias_s[BN];

    const int tid  = threadIdx.x;
    const int wid  = tid >> 5;
    const int lane = tid & 31;
    const int wm   = wid >> 2;        // 0..1  (64 rows each)
    const int wn   = wid & 3;         // 0..3  (32 cols each)

    const int n_tiles = NT / BN;                       // 32
    const int m0 = (int)(blockIdx.x >> 5) * BM;        // n-fast rasterization
    const int n0 = (int)(blockIdx.x & (n_tiles - 1)) * BN;

    const uint32_t smem = smem_u32(dynsmem);
    const uint32_t smem_last = smem + (NSTAGES - 1) * STAGE_BYTES;

    // independent prologue (overlaps with quant tail under PDL)
    for (int i = tid; i < BN; i += THREADS) bias_s[i] = bias[n0 + i];
    const float sx = FP8MAX / fmaxf(in_amax[0], AMAX_EPS);
    const float sw = FP8MAX / fmaxf(w_amax[0], AMAX_EPS);
    const float inv = 1.0f / (sx * sw);

    // ---- copy assignment: coalesced lane mapping, constant-folded addresses ----
    const int rowq = tid >> 3;                               // 0..31
    const uint32_t ch = (uint32_t)((tid & 7) << 4);          // 0..112
    const uint32_t chs = ch ^ (uint32_t)((rowq & 7) << 4);   // swizzle folded
    const uint8_t* gA = g_Xq + (size_t)(m0 + rowq) * KT + ch;
    const uint8_t* gB = g_Wq + (size_t)(n0 + rowq) * KT + ch;
    const uint32_t sAoff = (uint32_t)(rowq * BK) + chs;
    const uint32_t sBoff = (uint32_t)(A_BYTES + rowq * BK) + chs;

    auto issue_stage = [&](uint32_t sbase, const uint8_t* ga, const uint8_t* gb) {
        #pragma unroll
        for (int i = 0; i < 4; ++i) {
            cp_async16(sbase + sAoff + i * 4096, ga + (size_t)i * 32 * KT);
            cp_async16(sbase + sBoff + i * 4096, gb + (size_t)i * 32 * KT);
        }
    };

    // ---- per-lane ldmatrix offsets, ka order staggered by warp group ----
    const int a_row_l = (lane & 15);
    const uint32_t a_kchunk = (uint32_t)((lane >> 4) << 4);
    const int b_row_l = ((lane >> 4) << 3) + (lane & 7);
    const uint32_t b_kchunk = (uint32_t)(((lane >> 3) & 1) << 4);
    const int kao = (wid & 4) ? 2 : 0;   // warps 4-7 start at ka=2

    uint32_t a_base[4], b_base[2];
    uint32_t koAp[4], koBp[4];           // permuted K-offsets: slot j -> ka (kao+j)&3
    {
        const uint32_t a_xor = (uint32_t)(((wm * 64 + a_row_l) & 7) << 4);
        const uint32_t b_xor = (uint32_t)(((wn * 32 + b_row_l) & 7) << 4);
        #pragma unroll
        for (int am = 0; am < 4; ++am)
            a_base[am] = (uint32_t)((wm * 64 + am * 16 + a_row_l) * BK);
        #pragma unroll
        for (int bp = 0; bp < 2; ++bp)
            b_base[bp] = (uint32_t)((wn * 32 + bp * 16 + b_row_l) * BK + A_BYTES);
        #pragma unroll
        for (int j = 0; j < 4; ++j) {
            const int kk = (kao + j) & 3;
            koAp[j] = ((uint32_t)(kk * 32) + a_kchunk) ^ a_xor;
            koBp[j] = ((uint32_t)(kk * 32) + b_kchunk) ^ b_xor;
        }
    }

    float acc[4][4][4];
    #pragma unroll
    for (int i = 0; i < 4; ++i)
        #pragma unroll
        for (int j = 0; j < 4; ++j)
            #pragma unroll
            for (int k = 0; k < 4; ++k) acc[i][j][k] = 0.0f;

    // wait for quant data, then start the pipeline
    pdl_wait();

    #pragma unroll
    for (int s = 0; s < NSTAGES - 1; ++s) {
        issue_stage(smem + s * STAGE_BYTES, gA + s * BK, gB + s * BK);
        cp_commit();
    }

    auto compute_slot = [&](uint32_t cbase, int j) {
        uint32_t af[4][4];
        #pragma unroll
        for (int am = 0; am < 4; ++am)
            ldsm_x4(af[am][0], af[am][1], af[am][2], af[am][3],
                    cbase + a_base[am] + koAp[j]);
        uint32_t bf[2][4];
        #pragma unroll
        for (int bp = 0; bp < 2; ++bp)
            ldsm_x4(bf[bp][0], bf[bp][1], bf[bp][2], bf[bp][3],
                    cbase + b_base[bp] + koBp[j]);
        #pragma unroll
        for (int am = 0; am < 4; ++am) {
            #pragma unroll
            for (int an = 0; an < 4; ++an) {
                const int bp = an >> 1;
                const int hl = (an & 1) << 1;
                mma_e4m3(acc[am][an][0], acc[am][an][1], acc[am][an][2], acc[am][an][3],
                         af[am][0], af[am][1], af[am][2], af[am][3],
                         bf[bp][hl + 0], bf[bp][hl + 1]);
            }
        }
    };

    // ---- main loop: distance-2 prefetch, sync every iter ----
    uint32_t cbase = smem;
    uint32_t pbase = smem_last;
    const uint8_t* gnA = gA + (NSTAGES - 1) * BK;
    const uint8_t* gnB = gB + (NSTAGES - 1) * BK;

    for (int it = 0; it < K_ITERS; ++it) {
        cp_wait<NSTAGES - 2>();
        __syncthreads();

        compute_slot(cbase, 0);

        if (it < K_ITERS - (NSTAGES - 1)) {
            issue_stage(pbase, gnA, gnB);
            gnA += BK;
            gnB += BK;
        }
        cp_commit();
        pbase = (pbase == smem_last) ? smem : pbase + STAGE_BYTES;

        compute_slot(cbase, 1);
        compute_slot(cbase, 2);
        compute_slot(cbase, 3);
        cbase = (cbase == smem_last) ? smem : cbase + STAGE_BYTES;
    }

    // ---- epilogue: scale + bias + store ----
    const int row_base = m0 + wm * 64 + (lane >> 2);
    const int col_base = n0 + wn * 32 + (lane & 3) * 2;
    #pragma unroll
    for (int am = 0; am < 4; ++am) {
        #pragma unroll
        for (int an = 0; an < 4; ++an) {
            const int c = col_base + an * 8;
            const float b0 = bias_s[c - n0], b1 = bias_s[c - n0 + 1];
            const int r0 = row_base + am * 16;
            float2 v0 = make_float2(fmaf(acc[am][an][0], inv, b0),
                                    fmaf(acc[am][an][1], inv, b1));
            float2 v1 = make_float2(fmaf(acc[am][an][2], inv, b0),
                                    fmaf(acc[am][an][3], inv, b1));
            *(float2*)(out + (size_t)r0 * NT + c) = v0;
            *(float2*)(out + (size_t)(r0 + 8) * NT + c) = v1;
        }
    }
}

// ---------------- launch: quant, then GEMM with programmatic dependent launch ----------------
extern "C" void kernel_launch(void* const* d_in, const int* in_sizes, int n_in,
                              void* d_out, int out_size) {
    (void)in_sizes; (void)n_in;
    const float* x       = (const float*)d_in[0];
    const float* w       = (const float*)d_in[1];
    const float* bias    = (const float*)d_in[2];
    const float* in_amax = (const float*)d_in[3];
    const float* w_amax  = (const float*)d_in[4];
    float* out = (float*)d_out;

    quant_amax_kernel<<<Q_BLOCKS, 256>>>(x, w, in_amax, w_amax, out, out_size);

    cudaFuncSetAttribute(fp8_gemm_kernel,
                         cudaFuncAttributeMaxDynamicSharedMemorySize, DYN_SMEM);

    cudaLaunchConfig_t cfg = {};
    cfg.gridDim = dim3((MT / BM) * (NT / BN), 1, 1);
    cfg.blockDim = dim3(THREADS, 1, 1);
    cfg.dynamicSmemBytes = DYN_SMEM;
    cfg.stream = 0;
    cudaLaunchAttribute attrs[1];
    attrs[0].id = cudaLaunchAttributeProgrammaticStreamSerialization;
    attrs[0].val.programmaticStreamSerializationAllowed = 1;
    cfg.attrs = attrs;
    cfg.numAttrs = 1;

    cudaError_t err = cudaLaunchKernelEx(&cfg, fp8_gemm_kernel,
                                         bias, in_amax, w_amax, out);
    if (err != cudaSuccess) {
        // fallback: plain launch (still correct; quant completes first in stream order)
        fp8_gemm_kernel<<<(MT / BM) * (NT / BN), THREADS, DYN_SMEM>>>(
            bias, in_amax, w_amax, out);
    }
}